// round 5
// baseline (speedup 1.0000x reference)
#include <cuda_runtime.h>
#include <cuda_fp16.h>
#include <stdint.h>

// ---------------------------------------------------------------------------
// Problem constants
// ---------------------------------------------------------------------------
#define T_TOK 32768
#define E_DIM 1024
#define F_DIM 1024
#define NQ    10

// GEMM tiling: CTA 128x256, BK=32, 3-stage cp.async pipeline, mma.sync fp16
#define BM 128
#define BN 256
#define BK 32
#define NC (F_DIM / BK)        // 32 k-chunks
#define NSTAGE 3
#define ROWB 80                // 32 halves = 64B, padded to 80B (bank-conflict-free)
#define STG_A_HI 0
#define STG_A_LO (BM * ROWB)              // 10240
#define STG_B_HI (2 * BM * ROWB)          // 20480
#define STG_B_LO (2 * BM * ROWB + BN * ROWB)  // 40960
#define STG_BYTES (2 * BM * ROWB + 2 * BN * ROWB) // 61440
#define SMEM_BIAS (NSTAGE * STG_BYTES)    // 184320
#define SMEM_DYN  (SMEM_BIAS + BN * 4)    // 185344

// ---------------------------------------------------------------------------
// Scratch (static device globals -- no runtime allocation)
// ---------------------------------------------------------------------------
__device__ __half g_h_hi[(size_t)T_TOK * F_DIM];
__device__ __half g_h_lo[(size_t)T_TOK * F_DIM];
__device__ __half g_w_hi[(size_t)E_DIM * F_DIM];
__device__ __half g_w_lo[(size_t)E_DIM * F_DIM];

// ---------------------------------------------------------------------------
// PTX helpers (family-common only: cp.async + mma.sync, no tcgen05)
// ---------------------------------------------------------------------------
__device__ __forceinline__ uint32_t smem_u32(const void* p) {
    uint32_t a;
    asm("{ .reg .u64 t; cvta.to.shared.u64 t, %1; cvt.u32.u64 %0, t; }"
        : "=r"(a) : "l"(p));
    return a;
}

__device__ __forceinline__ void cp16(uint32_t s, const void* g) {
    asm volatile("cp.async.cg.shared.global [%0], [%1], 16;" :: "r"(s), "l"(g));
}
#define CP_COMMIT() asm volatile("cp.async.commit_group;" ::: "memory")
#define CP_WAIT(n)  asm volatile("cp.async.wait_group %0;" :: "n"(n) : "memory")

__device__ __forceinline__ uint32_t lds32(uint32_t addr) {
    uint32_t v;
    asm volatile("ld.shared.b32 %0, [%1];" : "=r"(v) : "r"(addr));
    return v;
}

// D(16x8) += A(16x16,row) * B(16x8,col), fp16 in / fp32 accum
__device__ __forceinline__ void mma16816(float* c, const uint32_t* a, const uint32_t* b) {
    asm volatile(
        "mma.sync.aligned.m16n8k16.row.col.f32.f16.f16.f32 "
        "{%0,%1,%2,%3}, {%4,%5,%6,%7}, {%8,%9}, {%0,%1,%2,%3};"
        : "+f"(c[0]), "+f"(c[1]), "+f"(c[2]), "+f"(c[3])
        : "r"(a[0]), "r"(a[1]), "r"(a[2]), "r"(a[3]), "r"(b[0]), "r"(b[1]));
}

// ---------------------------------------------------------------------------
// Kernel 1: z = cos(x[:, :10]); h = relu(z@W1^T + b1) -> fp16 hi/lo splits
// ---------------------------------------------------------------------------
#define TOK_PER_BLK 32
__global__ __launch_bounds__(256) void k_prep(const float* __restrict__ x,
                                              const float* __restrict__ W1,
                                              const float* __restrict__ b1) {
    __shared__ float sW1[F_DIM * NQ];
    __shared__ float sB1[F_DIM];
    __shared__ float sZ[TOK_PER_BLK * NQ];
    int tid = threadIdx.x;
    int t0 = blockIdx.x * TOK_PER_BLK;

    for (int i = tid; i < F_DIM * NQ; i += 256) sW1[i] = W1[i];
    for (int i = tid; i < F_DIM; i += 256) sB1[i] = b1[i];
    for (int i = tid; i < TOK_PER_BLK * NQ; i += 256) {
        int tt = i / NQ, q = i % NQ;
        sZ[i] = cosf(x[(size_t)(t0 + tt) * E_DIM + q]);
    }
    __syncthreads();

    for (int tt = 0; tt < TOK_PER_BLK; tt++) {
        float z[NQ];
#pragma unroll
        for (int q = 0; q < NQ; q++) z[q] = sZ[tt * NQ + q];
        size_t rowoff = (size_t)(t0 + tt) * F_DIM;
        for (int f = tid; f < F_DIM; f += 256) {
            float acc = sB1[f];
#pragma unroll
            for (int q = 0; q < NQ; q++) acc = fmaf(z[q], sW1[f * NQ + q], acc);
            float v = fmaxf(acc, 0.f);
            __half hi = __float2half_rn(v);
            float lo = v - __half2float(hi);
            g_h_hi[rowoff + f] = hi;
            g_h_lo[rowoff + f] = __float2half_rn(lo);
        }
    }
}

// ---------------------------------------------------------------------------
// Kernel 2: split W2 into fp16 hi/lo
// ---------------------------------------------------------------------------
__global__ __launch_bounds__(256) void k_wsplit(const float* __restrict__ W2) {
    int i = blockIdx.x * 256 + threadIdx.x;
    float w = W2[i];
    __half hi = __float2half_rn(w);
    g_w_hi[i] = hi;
    g_w_lo[i] = __float2half_rn(w - __half2float(hi));
}

// ---------------------------------------------------------------------------
// Kernel 3: out = h @ W2^T + b2, 3-pass fp16 split via mma.sync
// ---------------------------------------------------------------------------
extern __shared__ char smem[];

__device__ __forceinline__ void load_stage(uint32_t sb, int tid,
                                           const __half* Ahi, const __half* Alo,
                                           const __half* Bhi, const __half* Blo,
                                           int c, int buf) {
    uint32_t st = sb + (uint32_t)buf * STG_BYTES;
    int k0 = c * BK;
#pragma unroll
    for (int rep = 0; rep < 2; rep++) {           // A: 128 rows x 4 chunks
        int idx = tid + rep * 256;
        int r = idx >> 2, j = idx & 3;
        uint32_t so = (uint32_t)r * ROWB + (uint32_t)j * 16u;
        size_t g = (size_t)r * F_DIM + k0 + j * 8;
        cp16(st + STG_A_HI + so, Ahi + g);
        cp16(st + STG_A_LO + so, Alo + g);
    }
#pragma unroll
    for (int rep = 0; rep < 4; rep++) {           // B: 256 rows x 4 chunks
        int idx = tid + rep * 256;
        int r = idx >> 2, j = idx & 3;
        uint32_t so = (uint32_t)r * ROWB + (uint32_t)j * 16u;
        size_t g = (size_t)r * F_DIM + k0 + j * 8;
        cp16(st + STG_B_HI + so, Bhi + g);
        cp16(st + STG_B_LO + so, Blo + g);
    }
    CP_COMMIT();
}

__global__ void __launch_bounds__(256, 1)
k_gemm(const float* __restrict__ b2, float* __restrict__ out) {
    uint32_t sb = smem_u32(smem);
    int tid = threadIdx.x;
    int wid = tid >> 5, lane = tid & 31;
    int g = lane >> 2, qi = lane & 3;             // mma groupID / tid-in-group
    int warp_m = wid & 1, warp_n = wid >> 1;      // 2 x 4 warp grid, 64x64 tiles
    int n0 = blockIdx.x * BN;
    int m0 = blockIdx.y * BM;

    float* sB2 = (float*)(smem + SMEM_BIAS);
    for (int i = tid; i < BN; i += 256) sB2[i] = b2[n0 + i];

    const __half* Ahi = g_h_hi + (size_t)m0 * F_DIM;
    const __half* Alo = g_h_lo + (size_t)m0 * F_DIM;
    const __half* Bhi = g_w_hi + (size_t)n0 * F_DIM;
    const __half* Blo = g_w_lo + (size_t)n0 * F_DIM;

    float acc[4][8][4];
#pragma unroll
    for (int im = 0; im < 4; im++)
#pragma unroll
        for (int in = 0; in < 8; in++)
#pragma unroll
            for (int v = 0; v < 4; v++) acc[im][in][v] = 0.f;

    load_stage(sb, tid, Ahi, Alo, Bhi, Blo, 0, 0);
    load_stage(sb, tid, Ahi, Alo, Bhi, Blo, 1, 1);

    for (int c = 0; c < NC; c++) {
        CP_WAIT(1);                 // stage c landed
        __syncthreads();            // all warps done with buffer (c-1)%3
        if (c + 2 < NC)
            load_stage(sb, tid, Ahi, Alo, Bhi, Blo, c + 2, (c + 2) % NSTAGE);
        else
            CP_COMMIT();            // keep group accounting uniform

        uint32_t st = sb + (uint32_t)(c % NSTAGE) * STG_BYTES;
        uint32_t a_base = st + (uint32_t)(warp_m * 64 + g) * ROWB + (uint32_t)(qi * 4);
        uint32_t b_base = st + (uint32_t)(warp_n * 64 + g) * ROWB + (uint32_t)(qi * 4);

#pragma unroll
        for (int kk = 0; kk < 2; kk++) {
            uint32_t ko = (uint32_t)(kk * 32);    // 16 halves = 32 bytes

            uint32_t ah[4][4];
#pragma unroll
            for (int im = 0; im < 4; im++) {
                uint32_t a0 = a_base + STG_A_HI + ko + (uint32_t)(im * 16 * ROWB);
                ah[im][0] = lds32(a0);
                ah[im][1] = lds32(a0 + 8 * ROWB);
                ah[im][2] = lds32(a0 + 16);
                ah[im][3] = lds32(a0 + 8 * ROWB + 16);
            }
            uint32_t bh[8][2];
#pragma unroll
            for (int in = 0; in < 8; in++) {
                uint32_t b0 = b_base + STG_B_HI + ko + (uint32_t)(in * 8 * ROWB);
                bh[in][0] = lds32(b0);
                bh[in][1] = lds32(b0 + 16);
            }
            // pass 1: Ah * Bh
#pragma unroll
            for (int im = 0; im < 4; im++)
#pragma unroll
                for (int in = 0; in < 8; in++)
                    mma16816(acc[im][in], ah[im], bh[in]);

            uint32_t bl[8][2];
#pragma unroll
            for (int in = 0; in < 8; in++) {
                uint32_t b0 = b_base + STG_B_LO + ko + (uint32_t)(in * 8 * ROWB);
                bl[in][0] = lds32(b0);
                bl[in][1] = lds32(b0 + 16);
            }
            // pass 2: Ah * Bl
#pragma unroll
            for (int im = 0; im < 4; im++)
#pragma unroll
                for (int in = 0; in < 8; in++)
                    mma16816(acc[im][in], ah[im], bl[in]);

            uint32_t al[4][4];
#pragma unroll
            for (int im = 0; im < 4; im++) {
                uint32_t a0 = a_base + STG_A_LO + ko + (uint32_t)(im * 16 * ROWB);
                al[im][0] = lds32(a0);
                al[im][1] = lds32(a0 + 8 * ROWB);
                al[im][2] = lds32(a0 + 16);
                al[im][3] = lds32(a0 + 8 * ROWB + 16);
            }
            // pass 3: Al * Bh
#pragma unroll
            for (int im = 0; im < 4; im++)
#pragma unroll
                for (int in = 0; in < 8; in++)
                    mma16816(acc[im][in], al[im], bh[in]);
        }
    }

    // Epilogue: D[row][col] = acc + b2[col]
    int mw = m0 + warp_m * 64;
    int nw_rel = warp_n * 64;                     // n relative to n0
#pragma unroll
    for (int im = 0; im < 4; im++) {
        int r0 = mw + im * 16 + g;
#pragma unroll
        for (int in = 0; in < 8; in++) {
            int cr = nw_rel + in * 8 + 2 * qi;
            float bx = sB2[cr], by = sB2[cr + 1];
            float2 v0 = {acc[im][in][0] + bx, acc[im][in][1] + by};
            float2 v1 = {acc[im][in][2] + bx, acc[im][in][3] + by};
            *(float2*)(out + (size_t)r0 * E_DIM + n0 + cr) = v0;
            *(float2*)(out + (size_t)(r0 + 8) * E_DIM + n0 + cr) = v1;
        }
    }
}

// ---------------------------------------------------------------------------
// Launch
// ---------------------------------------------------------------------------
extern "C" void kernel_launch(void* const* d_in, const int* in_sizes, int n_in,
                              void* d_out, int out_size) {
    const float* x  = (const float*)d_in[0];
    // d_in[1] = rz_theta : drops out analytically (RZ phases cancel in <Z>)
    const float* W1 = (const float*)d_in[2];
    const float* b1 = (const float*)d_in[3];
    const float* W2 = (const float*)d_in[4];
    const float* b2 = (const float*)d_in[5];
    float* out = (float*)d_out;

    k_prep<<<T_TOK / TOK_PER_BLK, 256>>>(x, W1, b1);
    k_wsplit<<<(E_DIM * F_DIM) / 256, 256>>>(W2);

    cudaFuncSetAttribute(k_gemm, cudaFuncAttributeMaxDynamicSharedMemorySize, SMEM_DYN);
    k_gemm<<<dim3(E_DIM / BN, T_TOK / BM), 256, SMEM_DYN>>>(b2, out);
}